// round 16
// baseline (speedup 1.0000x reference)
#include <cuda_runtime.h>
#include <cuda_bf16.h>
#include <cuda_fp16.h>
#include <cuda_fp8.h>
#include <cstdint>
#include <math.h>

#define NUI 4096
#define NVI 4096
#define NC 5
#define H0 256
#define H1 128
#define DIN 512
#define SIDE 1024
#define NE 4096
#define CATW (H0 + DIN)      // 768
#define KF   (3 * H1)        // 384
#define KFEAT (3 * SIDE)     // 3072
#define KCAT (3 * CATW)      // 2304

__device__ uint8_t d_code[(size_t)NUI * NVI];
__device__ uint8_t d_cg [(size_t)NE * NE];
__device__ uint8_t d_cgT[(size_t)NE * NE];
__device__ uint8_t d_cu8[(size_t)NC * NUI * H0];
__device__ uint8_t d_cv8[(size_t)NC * NVI * H0];
__device__ float   d_uh [(size_t)NE * H1];
__device__ float   d_PT [2 * H1 * H1];
__device__ __nv_bfloat16 d_T0s[(size_t)NE * KF];
__device__ __nv_bfloat16 d_T1s[(size_t)NE * KF];
__device__ __nv_bfloat16 d_vhs[(size_t)NE * KF];
__device__ __nv_bfloat16 d_ufs [(size_t)NE * KFEAT];
__device__ __nv_bfloat16 d_vfs [(size_t)NE * KFEAT];
__device__ __nv_bfloat16 d_w1us[(size_t)DIN * KFEAT];
__device__ __nv_bfloat16 d_w1vs[(size_t)DIN * KFEAT];
__device__ __nv_bfloat16 d_ucats[(size_t)NE * KCAT];
__device__ __nv_bfloat16 d_vcats[(size_t)NE * KCAT];
__device__ __nv_bfloat16 d_w2us[(size_t)H1 * KCAT];
__device__ __nv_bfloat16 d_w2vs[(size_t)H1 * KCAT];
__device__ double  g_loss, g_se;
__device__ int     g_cnt;

__device__ __forceinline__ uint32_t smaddr(const void* p) {
    return (uint32_t)__cvta_generic_to_shared(p);
}
__device__ __forceinline__ void ldsm4(uint32_t& r0, uint32_t& r1, uint32_t& r2, uint32_t& r3,
                                      uint32_t a) {
    asm volatile("ldmatrix.sync.aligned.m8n8.x4.shared.b16 {%0,%1,%2,%3}, [%4];\n"
                 : "=r"(r0), "=r"(r1), "=r"(r2), "=r"(r3) : "r"(a));
}
__device__ __forceinline__ void mma16816(float* d, const uint32_t* a, const uint32_t* b) {
    asm volatile("mma.sync.aligned.m16n8k16.row.col.f32.bf16.bf16.f32 "
                 "{%0,%1,%2,%3}, {%4,%5,%6,%7}, {%8,%9}, {%0,%1,%2,%3};\n"
                 : "+f"(d[0]), "+f"(d[1]), "+f"(d[2]), "+f"(d[3])
                 : "r"(a[0]), "r"(a[1]), "r"(a[2]), "r"(a[3]), "r"(b[0]), "r"(b[1]));
}
__device__ __forceinline__ __half2 fp8x2_to_h2(uint32_t w16) {
    __half2_raw r = __nv_cvt_fp8x2_to_halfraw2((__nv_fp8x2_storage_t)w16, __NV_E4M3);
    return *reinterpret_cast<__half2*>(&r);
}
__device__ __forceinline__ uint32_t pack_bf(float x0, float x1) {
    uint32_t u0 = (uint32_t)__bfloat16_as_ushort(__float2bfloat16(x0));
    uint32_t u1 = (uint32_t)__bfloat16_as_ushort(__float2bfloat16(x1));
    return u0 | (u1 << 16);
}
__device__ __forceinline__ float bf_hi(float x) {
    return __bfloat162float(__float2bfloat16(x));
}
__device__ __forceinline__ void split_store2(__nv_bfloat16* S, int SK, int r, int col,
                                             float x0, float x1, int isB) {
    uint32_t hh = pack_bf(x0, x1);
    uint32_t ll = pack_bf(x0 - bf_hi(x0), x1 - bf_hi(x1));
    __nv_bfloat16* d = S + (size_t)r * 3 * SK + col;
    *(uint32_t*)d = hh;
    *(uint32_t*)(d + SK) = isB ? ll : hh;
    *(uint32_t*)(d + 2 * SK) = isB ? hh : ll;
}

__global__ void code_kernel(const float4* __restrict__ adj) {
    size_t t = (size_t)blockIdx.x * 256 + threadIdx.x;
    const size_t S4 = (size_t)NUI * NVI / 4;
    int gx = 0, gy = 0, gz = 0, gw = 0;
#pragma unroll
    for (int c = 0; c < NC; ++c) {
        float4 vv = adj[(size_t)c * S4 + t];
        if (vv.x > 0.5f) gx = c + 1;
        if (vv.y > 0.5f) gy = c + 1;
        if (vv.z > 0.5f) gz = c + 1;
        if (vv.w > 0.5f) gw = c + 1;
    }
    ((uchar4*)d_code)[t] = make_uchar4(gx, gy, gz, gw);
}

__global__ __launch_bounds__(256) void gatherrow_kernel(const int* __restrict__ u,
                                                        const int* __restrict__ v) {
    __shared__ uint8_t srow[NVI];
    int i = blockIdx.x, tid = threadIdx.x;
    const uint32_t* crow = (const uint32_t*)(d_code + (size_t)u[i] * NVI);
    for (int t = tid; t < NVI / 4; t += 256)
        ((uint32_t*)srow)[t] = crow[t];
    __syncthreads();
    uint8_t* orow = d_cg + (size_t)i * NE;
    for (int j = tid * 4; j < NE; j += 1024) {
        uchar4 g = make_uchar4(srow[v[j]], srow[v[j + 1]], srow[v[j + 2]], srow[v[j + 3]]);
        *(uchar4*)(orow + j) = g;
    }
}

__global__ void transb_kernel() {
    __shared__ uint8_t tile[32][33];
    int tx = threadIdx.x, ty = threadIdx.y;
    int i = blockIdx.y * 32 + ty, j = blockIdx.x * 32 + tx;
    tile[ty][tx] = d_cg[(size_t)i * NE + j];
    __syncthreads();
    d_cgT[(size_t)(blockIdx.x * 32 + ty) * NE + blockIdx.y * 32 + tx] = tile[tx][ty];
}

__global__ void cumsum8_kernel(const float* __restrict__ w, uint8_t* __restrict__ out, int n) {
    int idx = blockIdx.x * blockDim.x + threadIdx.x;
    if (idx >= n) return;
    float s = 0.f;
#pragma unroll
    for (int c = 0; c < NC; ++c) {
        s += w[(size_t)c * n + idx];
        out[(size_t)c * n + idx] =
            (uint8_t)__nv_cvt_float_to_fp8(s, __NV_SATFINITE, __NV_E4M3);
    }
}

__global__ void zero_kernel() { g_loss = 0.0; g_se = 0.0; g_cnt = 0; }

// graph conv: sparse gather-sum over fp8 tables (champion form)
__global__ __launch_bounds__(256) void convfp8_kernel(const int* __restrict__ uidx,
                                                      const int* __restrict__ vidx) {
    __shared__ uint8_t rs[NE];
    __shared__ int list[NE];
    __shared__ int wsum[8], wbase[8];
    __shared__ float part[16][H0];
    int z = blockIdx.y;
    const uint8_t* cgm = z ? d_cgT : d_cg;
    const int* idx = z ? uidx : vidx;
    const uint8_t* tab = z ? d_cu8 : d_cv8;
    __nv_bfloat16* outs = z ? d_vcats : d_ucats;

    int i = blockIdx.x, tid = threadIdx.x;
    int lane = tid & 31, wid5 = tid >> 5;
    const uint8_t* row = cgm + (size_t)i * NE;
    for (int t = tid; t < NE / 4; t += 256)
        ((uint32_t*)rs)[t] = ((const uint32_t*)row)[t];
    __syncthreads();

    int j0 = tid * 16;
    int local = 0;
#pragma unroll
    for (int t = 0; t < 16; ++t) if (rs[j0 + t]) local++;
    int val = local;
#pragma unroll
    for (int s = 1; s < 32; s <<= 1) {
        int t = __shfl_up_sync(0xFFFFFFFFu, val, s);
        if (lane >= s) val += t;
    }
    if (lane == 31) wsum[wid5] = val;
    __syncthreads();
    if (tid < 8) {
        int b = 0;
        for (int q = 0; q < tid; ++q) b += wsum[q];
        wbase[tid] = b;
    }
    __syncthreads();
    int pos = wbase[wid5] + val - local;
    int total = wbase[7] + wsum[7];
    for (int t = 0; t < 16; ++t) {
        int g = rs[j0 + t];
        if (g) list[pos++] = (g - 1) * NVI + idx[j0 + t];
    }
    __syncthreads();

    int rg = tid >> 4;
    int hbase = (tid & 15) * 16;
    float facc[16];
#pragma unroll
    for (int q = 0; q < 16; ++q) facc[q] = 0.f;
    int jj = rg;
    while (jj + 256 <= total) {
        __half2 h[8];
#pragma unroll
        for (int q = 0; q < 8; ++q) h[q] = __float2half2_rn(0.f);
#pragma unroll
        for (int w8 = 0; w8 < 16; ++w8) {
            const uint4 w = *(const uint4*)(tab + (size_t)list[jj + w8 * 16] * H0 + hbase);
            h[0] = __hadd2(h[0], fp8x2_to_h2(w.x & 0xFFFFu));
            h[1] = __hadd2(h[1], fp8x2_to_h2(w.x >> 16));
            h[2] = __hadd2(h[2], fp8x2_to_h2(w.y & 0xFFFFu));
            h[3] = __hadd2(h[3], fp8x2_to_h2(w.y >> 16));
            h[4] = __hadd2(h[4], fp8x2_to_h2(w.z & 0xFFFFu));
            h[5] = __hadd2(h[5], fp8x2_to_h2(w.z >> 16));
            h[6] = __hadd2(h[6], fp8x2_to_h2(w.w & 0xFFFFu));
            h[7] = __hadd2(h[7], fp8x2_to_h2(w.w >> 16));
        }
        jj += 256;
#pragma unroll
        for (int q = 0; q < 8; ++q) {
            float2 f = __half22float2(h[q]);
            facc[2 * q] += f.x; facc[2 * q + 1] += f.y;
        }
    }
    while (jj < total) {
        __half2 h[8];
#pragma unroll
        for (int q = 0; q < 8; ++q) h[q] = __float2half2_rn(0.f);
        int lim = jj + 128;
        for (; jj < lim && jj < total; jj += 16) {
            const uint4 w = *(const uint4*)(tab + (size_t)list[jj] * H0 + hbase);
            h[0] = __hadd2(h[0], fp8x2_to_h2(w.x & 0xFFFFu));
            h[1] = __hadd2(h[1], fp8x2_to_h2(w.x >> 16));
            h[2] = __hadd2(h[2], fp8x2_to_h2(w.y & 0xFFFFu));
            h[3] = __hadd2(h[3], fp8x2_to_h2(w.y >> 16));
            h[4] = __hadd2(h[4], fp8x2_to_h2(w.z & 0xFFFFu));
            h[5] = __hadd2(h[5], fp8x2_to_h2(w.z >> 16));
            h[6] = __hadd2(h[6], fp8x2_to_h2(w.w & 0xFFFFu));
            h[7] = __hadd2(h[7], fp8x2_to_h2(w.w >> 16));
        }
#pragma unroll
        for (int q = 0; q < 8; ++q) {
            float2 f = __half22float2(h[q]);
            facc[2 * q] += f.x; facc[2 * q + 1] += f.y;
        }
    }
#pragma unroll
    for (int q = 0; q < 16; q += 4)
        *(float4*)&part[rg][hbase + q] = make_float4(facc[q], facc[q + 1],
                                                     facc[q + 2], facc[q + 3]);
    __syncthreads();
    float s = 0.f;
#pragma unroll
    for (int r = 0; r < 16; ++r) s += part[r][tid];
    float inv = total ? 1.f / (float)total : 0.f;
    float zv = fmaxf(s * inv, 0.f);
    __nv_bfloat16 hb = __float2bfloat16(zv);
    __nv_bfloat16 lb = __float2bfloat16(zv - __bfloat162float(hb));
    __nv_bfloat16* d = outs + (size_t)i * KCAT + tid;
    d[0] = hb; d[CATW] = hb; d[2 * CATW] = lb;
}

__global__ void splitr_kernel(const float* __restrict__ src, int K,
                              const int* __restrict__ idx,
                              __nv_bfloat16* __restrict__ dst, int isB) {
    int t = blockIdx.x * 256 + threadIdx.x;
    int q = t * 4;
    int row = q / K, k = q - row * K;
    const float4 x = *(const float4*)(src + (size_t)(idx ? idx[row] : row) * K + k);
    uint2 hh = make_uint2(pack_bf(x.x, x.y), pack_bf(x.z, x.w));
    uint2 ll = make_uint2(pack_bf(x.x - bf_hi(x.x), x.y - bf_hi(x.y)),
                          pack_bf(x.z - bf_hi(x.z), x.w - bf_hi(x.w)));
    __nv_bfloat16* d = dst + (size_t)row * 3 * K + k;
    *(uint2*)d = hh;
    *(uint2*)(d + K) = isB ? ll : hh;
    *(uint2*)(d + 2 * K) = isB ? hh : ll;
}

// batched (z=2) double-buffered bf16 HMMA GEMM with optional fp32 C / split-bf16 S output.
__global__ __launch_bounds__(256) void gemmbf2_kernel(
    const __nv_bfloat16* __restrict__ A0, const __nv_bfloat16* __restrict__ B0,
    const float* __restrict__ bias0, float* __restrict__ C0,
    __nv_bfloat16* __restrict__ S0, int SisB0,
    const __nv_bfloat16* __restrict__ A1, const __nv_bfloat16* __restrict__ B1,
    const float* __restrict__ bias1, float* __restrict__ C1,
    __nv_bfloat16* __restrict__ S1, int SisB1,
    int ldc, int KS, int doRelu, int SK, int SOFF) {
    __shared__ __align__(16) __nv_bfloat16 As[2][128][40];
    __shared__ __align__(16) __nv_bfloat16 Bs[2][64][40];
    const uint32_t AOFF = 128 * 40 * 2;
    const uint32_t BOFF = 64 * 40 * 2;
    int z = blockIdx.z;
    const __nv_bfloat16* A = z ? A1 : A0;
    const __nv_bfloat16* B = z ? B1 : B0;
    const float* bias = z ? bias1 : bias0;
    float* C = z ? C1 : C0;
    __nv_bfloat16* S = z ? S1 : S0;
    int SisB = z ? SisB1 : SisB0;

    int bm = blockIdx.y * 128, bn = blockIdx.x * 64;
    int tid = threadIdx.x, lane = tid & 31, warp = tid >> 5;
    int wm = (warp & 3) * 32, wn = (warp >> 2) * 32;
    int rowL = tid >> 1, segL = (tid & 1) * 16;

    float acc[2][4][4] = {};
    uint32_t aAddr[2], bAddr[2];
#pragma unroll
    for (int f = 0; f < 2; ++f)
        aAddr[f] = smaddr(&As[0][wm + f * 16 + (lane & 15)][(lane >> 4) * 8]);
#pragma unroll
    for (int p = 0; p < 2; ++p)
        bAddr[p] = smaddr(&Bs[0][wn + p * 16 + (lane & 7) + ((lane >> 4) & 1) * 8]
                             [((lane >> 3) & 1) * 8]);

    const __nv_bfloat16* arow = A + (size_t)(bm + rowL) * KS + segL;
    const __nv_bfloat16* brow = B + (size_t)(bn + (rowL & 63)) * KS + segL;

    {
        uint4 a0 = ((const uint4*)arow)[0], a1 = ((const uint4*)arow)[1];
        ((uint4*)&As[0][rowL][segL])[0] = a0; ((uint4*)&As[0][rowL][segL])[1] = a1;
        if (tid < 128) {
            uint4 b0 = ((const uint4*)brow)[0], b1 = ((const uint4*)brow)[1];
            ((uint4*)&Bs[0][rowL][segL])[0] = b0; ((uint4*)&Bs[0][rowL][segL])[1] = b1;
        }
    }
    __syncthreads();

    int cur = 0;
    for (int k0 = 0; k0 < KS; k0 += 32) {
        bool nxt = (k0 + 32 < KS);
        uint4 pa0, pa1, pb0, pb1;
        if (nxt) {
            pa0 = ((const uint4*)(arow + k0 + 32))[0];
            pa1 = ((const uint4*)(arow + k0 + 32))[1];
            if (tid < 128) {
                pb0 = ((const uint4*)(brow + k0 + 32))[0];
                pb1 = ((const uint4*)(brow + k0 + 32))[1];
            }
        }
        uint32_t ao = cur ? AOFF : 0, bo = cur ? BOFF : 0;
#pragma unroll
        for (int ks = 0; ks < 2; ++ks) {
            uint32_t a[2][4], b[4][2];
            ldsm4(a[0][0], a[0][1], a[0][2], a[0][3], aAddr[0] + ao + ks * 32);
            ldsm4(a[1][0], a[1][1], a[1][2], a[1][3], aAddr[1] + ao + ks * 32);
#pragma unroll
            for (int p = 0; p < 2; ++p) {
                uint32_t r0, r1, r2, r3;
                ldsm4(r0, r1, r2, r3, bAddr[p] + bo + ks * 32);
                b[2 * p][0] = r0; b[2 * p][1] = r1;
                b[2 * p + 1][0] = r2; b[2 * p + 1][1] = r3;
            }
#pragma unroll
            for (int f = 0; f < 2; ++f)
#pragma unroll
                for (int e = 0; e < 4; ++e)
                    mma16816(acc[f][e], a[f], b[e]);
        }
        if (nxt) {
            int nx = cur ^ 1;
            ((uint4*)&As[nx][rowL][segL])[0] = pa0; ((uint4*)&As[nx][rowL][segL])[1] = pa1;
            if (tid < 128) {
                ((uint4*)&Bs[nx][rowL][segL])[0] = pb0; ((uint4*)&Bs[nx][rowL][segL])[1] = pb1;
            }
        }
        __syncthreads();
        cur ^= 1;
    }
#pragma unroll
    for (int f = 0; f < 2; ++f) {
        int r0 = bm + wm + f * 16 + (lane >> 2);
#pragma unroll
        for (int e = 0; e < 4; ++e) {
            int col = bn + wn + e * 8 + (lane & 3) * 2;
            float b0 = bias ? bias[col] : 0.f;
            float b1 = bias ? bias[col + 1] : 0.f;
            float c00 = acc[f][e][0] + b0, c01 = acc[f][e][1] + b1;
            float c10 = acc[f][e][2] + b0, c11 = acc[f][e][3] + b1;
            if (doRelu) {
                c00 = fmaxf(c00, 0.f); c01 = fmaxf(c01, 0.f);
                c10 = fmaxf(c10, 0.f); c11 = fmaxf(c11, 0.f);
            }
            if (C) {
                *(float2*)&C[(size_t)r0 * ldc + col] = make_float2(c00, c01);
                *(float2*)&C[(size_t)(r0 + 8) * ldc + col] = make_float2(c10, c11);
            }
            if (S) {
                split_store2(S, SK, r0,     SOFF + col, c00, c01, SisB);
                split_store2(S, SK, r0 + 8, SOFF + col, c10, c11, SisB);
            }
        }
    }
}

__global__ void gemm2_kernel(const float* __restrict__ A,
                             const float* __restrict__ Pt,
                             __nv_bfloat16* __restrict__ S0,
                             __nv_bfloat16* __restrict__ S1) {
    __shared__ float As[16][64];
    __shared__ float Bs[16][64];
    int z = blockIdx.z;
    const float* B = Pt + (size_t)z * H1 * H1;
    __nv_bfloat16* S = z ? S1 : S0;
    int bm = blockIdx.y * 64, bn = blockIdx.x * 64;
    int tid = threadIdx.x;
    int tx = tid & 15, ty = tid >> 4;
    int lrow = tid >> 2, lk = (tid & 3) * 4;
    const float* Ap = A + (size_t)(bm + lrow) * H1 + lk;
    const float* Bp = B + (size_t)(bn + lrow) * H1 + lk;
    float acc[4][4] = {};
    for (int k0 = 0; k0 < H1; k0 += 16) {
        float4 av = *(const float4*)(Ap + k0);
        float4 bv = *(const float4*)(Bp + k0);
        __syncthreads();
        As[lk + 0][lrow] = av.x; As[lk + 1][lrow] = av.y;
        As[lk + 2][lrow] = av.z; As[lk + 3][lrow] = av.w;
        Bs[lk + 0][lrow] = bv.x; Bs[lk + 1][lrow] = bv.y;
        Bs[lk + 2][lrow] = bv.z; Bs[lk + 3][lrow] = bv.w;
        __syncthreads();
#pragma unroll
        for (int k = 0; k < 16; ++k) {
            float4 a = *(const float4*)&As[k][ty * 4];
            float4 b = *(const float4*)&Bs[k][tx * 4];
            float af[4] = {a.x, a.y, a.z, a.w};
            float bf[4] = {b.x, b.y, b.z, b.w};
#pragma unroll
            for (int p = 0; p < 4; ++p)
#pragma unroll
                for (int q = 0; q < 4; ++q)
                    acc[p][q] = fmaf(af[p], bf[q], acc[p][q]);
        }
    }
#pragma unroll
    for (int p = 0; p < 4; ++p) {
        int row = bm + ty * 4 + p;
        int col = bn + tx * 4;
        split_store2(S, H1, row, col,     acc[p][0], acc[p][1], 0);
        split_store2(S, H1, row, col + 2, acc[p][2], acc[p][3], 0);
    }
}

__global__ void transP_kernel(const float* __restrict__ P) {
    int t = blockIdx.x * 256 + threadIdx.x;
    int b = t >> 14, rem = t & 16383;
    int d = rem >> 7, e = rem & 127;
    d_PT[(size_t)b * 16384 + e * 128 + d] = P[t];
}

__device__ __forceinline__ float fast_exp(float x) {
    float t = x * 1.4426950408889634f;
    float r = rintf(t);
    float f = t - r;
    float p = 1.535336188319500e-4f;
    p = fmaf(p, f, 1.339887440266574e-3f);
    p = fmaf(p, f, 9.618437357674640e-3f);
    p = fmaf(p, f, 5.550332471162809e-2f);
    p = fmaf(p, f, 2.402264791363012e-1f);
    p = fmaf(p, f, 6.931472028550421e-1f);
    p = fmaf(p, f, 1.0f);
    int e = (int)r;
    if (e < -126) e = -126;
    return p * __int_as_float((e + 127) << 23);
}

__device__ __forceinline__ void decode_pair(float s0a, float s1a, float s0b, float s1b,
                                            const float* a0c, const float* a1c,
                                            int i, int jc, float* __restrict__ out,
                                            float& lloss, float& lsse, int& lcnt) {
    float la[5], lb[5], mxa = -1e30f, mxb = -1e30f;
#pragma unroll
    for (int c = 0; c < 5; ++c) {
        la[c] = fmaf(a0c[c], s0a, a1c[c] * s1a);
        lb[c] = fmaf(a0c[c], s0b, a1c[c] * s1b);
        mxa = fmaxf(mxa, la[c]);
        mxb = fmaxf(mxb, lb[c]);
    }
    float ssa = 0.f, ssb = 0.f, mha = 0.f, mhb = 0.f;
#pragma unroll
    for (int c = 0; c < 5; ++c) {
        float ea = fast_exp(la[c] - mxa);
        float eb = fast_exp(lb[c] - mxb);
        ssa += ea; ssb += eb;
        mha = fmaf((float)(c + 1), ea, mha);
        mhb = fmaf((float)(c + 1), eb, mhb);
    }
    mha *= 1.f / ssa;
    mhb *= 1.f / ssb;
    *(float2*)&out[(size_t)i * NE + jc] = make_float2(mha, mhb);
    uchar2 g2 = *(const uchar2*)(d_cg + (size_t)i * NE + jc);
    if (g2.x) {
        float lse = mxa + __logf(ssa);
        float lg = la[0];
#pragma unroll
        for (int c = 1; c < 5; ++c) if (g2.x == c + 1) lg = la[c];
        lloss += lse - lg;
        float dd = mha - (float)g2.x;
        lsse += dd * dd;
        lcnt++;
    }
    if (g2.y) {
        float lse = mxb + __logf(ssb);
        float lg = lb[0];
#pragma unroll
        for (int c = 1; c < 5; ++c) if (g2.y == c + 1) lg = lb[c];
        lloss += lse - lg;
        float dd = mhb - (float)g2.y;
        lsse += dd * dd;
        lcnt++;
    }
}

// fused decoder on HMMA (split-bf16), BM=64 x BN=128, double-buffered smem
__global__ __launch_bounds__(256) void finalmma_kernel(const float* __restrict__ avec,
                                                       float* __restrict__ out) {
    __shared__ __align__(16) __nv_bfloat16 As0[2][64][40];
    __shared__ __align__(16) __nv_bfloat16 As1[2][64][40];
    __shared__ __align__(16) __nv_bfloat16 Bs[2][128][40];
    const uint32_t A0OFF = 64 * 40 * 2;
    const uint32_t B0OFF = 128 * 40 * 2;
    int bm = blockIdx.y * 64, bn = blockIdx.x * 128;
    int tid = threadIdx.x, lane = tid & 31, warp = tid >> 5;
    int wm = (warp & 1) * 32, wn = (warp >> 1) * 32;
    int rowL = tid >> 1, segL = (tid & 1) * 16;

    float acc0[2][4][4] = {}, acc1[2][4][4] = {};
    uint32_t a0Addr[2], a1Addr[2], bAddr[2];
#pragma unroll
    for (int f = 0; f < 2; ++f) {
        a0Addr[f] = smaddr(&As0[0][wm + f * 16 + (lane & 15)][(lane >> 4) * 8]);
        a1Addr[f] = smaddr(&As1[0][wm + f * 16 + (lane & 15)][(lane >> 4) * 8]);
    }
#pragma unroll
    for (int p = 0; p < 2; ++p)
        bAddr[p] = smaddr(&Bs[0][wn + p * 16 + (lane & 7) + ((lane >> 4) & 1) * 8]
                             [((lane >> 3) & 1) * 8]);

    const __nv_bfloat16* a0row = d_T0s + (size_t)(bm + (rowL & 63)) * KF + segL;
    const __nv_bfloat16* a1row = d_T1s + (size_t)(bm + (rowL & 63)) * KF + segL;
    const __nv_bfloat16* brow  = d_vhs + (size_t)(bn + rowL) * KF + segL;

    // preload tile 0 into stage 0
    if (tid < 128) {
        ((uint4*)&As0[0][rowL][segL])[0] = ((const uint4*)a0row)[0];
        ((uint4*)&As0[0][rowL][segL])[1] = ((const uint4*)a0row)[1];
        ((uint4*)&As1[0][rowL][segL])[0] = ((const uint4*)a1row)[0];
        ((uint4*)&As1[0][rowL][segL])[1] = ((const uint4*)a1row)[1];
    }
    ((uint4*)&Bs[0][rowL][segL])[0] = ((const uint4*)brow)[0];
    ((uint4*)&Bs[0][rowL][segL])[1] = ((const uint4*)brow)[1];
    __syncthreads();

    int cur = 0;
    for (int k0 = 0; k0 < KF; k0 += 32) {
        bool nxt = (k0 + 32 < KF);
        uint4 p0a, p0b, p1a, p1b, pba, pbb;
        if (nxt) {
            if (tid < 128) {
                p0a = ((const uint4*)(a0row + k0 + 32))[0];
                p0b = ((const uint4*)(a0row + k0 + 32))[1];
                p1a = ((const uint4*)(a1row + k0 + 32))[0];
                p1b = ((const uint4*)(a1row + k0 + 32))[1];
            }
            pba = ((const uint4*)(brow + k0 + 32))[0];
            pbb = ((const uint4*)(brow + k0 + 32))[1];
        }
        uint32_t ao = cur ? A0OFF : 0, bo = cur ? B0OFF : 0;
#pragma unroll
        for (int ks = 0; ks < 2; ++ks) {
            uint32_t a0[2][4], a1[2][4], b[4][2];
            ldsm4(a0[0][0], a0[0][1], a0[0][2], a0[0][3], a0Addr[0] + ao + ks * 32);
            ldsm4(a0[1][0], a0[1][1], a0[1][2], a0[1][3], a0Addr[1] + ao + ks * 32);
            ldsm4(a1[0][0], a1[0][1], a1[0][2], a1[0][3], a1Addr[0] + ao + ks * 32);
            ldsm4(a1[1][0], a1[1][1], a1[1][2], a1[1][3], a1Addr[1] + ao + ks * 32);
#pragma unroll
            for (int p = 0; p < 2; ++p) {
                uint32_t r0, r1, r2, r3;
                ldsm4(r0, r1, r2, r3, bAddr[p] + bo + ks * 32);
                b[2 * p][0] = r0; b[2 * p][1] = r1;
                b[2 * p + 1][0] = r2; b[2 * p + 1][1] = r3;
            }
#pragma unroll
            for (int f = 0; f < 2; ++f)
#pragma unroll
                for (int e = 0; e < 4; ++e) {
                    mma16816(acc0[f][e], a0[f], b[e]);
                    mma16816(acc1[f][e], a1[f], b[e]);
                }
        }
        if (nxt) {
            int nx = cur ^ 1;
            if (tid < 128) {
                ((uint4*)&As0[nx][rowL][segL])[0] = p0a;
                ((uint4*)&As0[nx][rowL][segL])[1] = p0b;
                ((uint4*)&As1[nx][rowL][segL])[0] = p1a;
                ((uint4*)&As1[nx][rowL][segL])[1] = p1b;
            }
            ((uint4*)&Bs[nx][rowL][segL])[0] = pba;
            ((uint4*)&Bs[nx][rowL][segL])[1] = pbb;
        }
        __syncthreads();
        cur ^= 1;
    }

    float a0c[5], a1c[5];
#pragma unroll
    for (int c = 0; c < 5; ++c) { a0c[c] = avec[c]; a1c[c] = avec[5 + c]; }
    float lloss = 0.f, lsse = 0.f;
    int lcnt = 0;
#pragma unroll
    for (int f = 0; f < 2; ++f) {
        int i0 = bm + wm + f * 16 + (lane >> 2);
#pragma unroll
        for (int e = 0; e < 4; ++e) {
            int jc = bn + wn + e * 8 + (lane & 3) * 2;
            decode_pair(acc0[f][e][0], acc1[f][e][0], acc0[f][e][1], acc1[f][e][1],
                        a0c, a1c, i0, jc, out, lloss, lsse, lcnt);
            decode_pair(acc0[f][e][2], acc1[f][e][2], acc0[f][e][3], acc1[f][e][3],
                        a0c, a1c, i0 + 8, jc, out, lloss, lsse, lcnt);
        }
    }

    __shared__ double red[256];
    __shared__ int redi[256];
    __syncthreads();
    red[tid] = (double)lloss; __syncthreads();
    for (int s = 128; s > 0; s >>= 1) { if (tid < s) red[tid] += red[tid + s]; __syncthreads(); }
    if (tid == 0) atomicAdd(&g_loss, red[0]);
    __syncthreads();
    red[tid] = (double)lsse; __syncthreads();
    for (int s = 128; s > 0; s >>= 1) { if (tid < s) red[tid] += red[tid + s]; __syncthreads(); }
    if (tid == 0) atomicAdd(&g_se, red[0]);
    __syncthreads();
    redi[tid] = lcnt; __syncthreads();
    for (int s = 128; s > 0; s >>= 1) { if (tid < s) redi[tid] += redi[tid + s]; __syncthreads(); }
    if (tid == 0) atomicAdd(&g_cnt, redi[0]);
}

__global__ void fin_kernel(float* __restrict__ out) {
    double n = (g_cnt > 0) ? (double)g_cnt : 1.0;
    out[(size_t)NE * NE + 0] = (float)(g_loss / n);
    out[(size_t)NE * NE + 1] = (float)sqrt(g_se / n);
}

extern "C" void kernel_launch(void* const* d_in, const int* in_sizes, int n_in,
                              void* d_out, int out_size) {
    const int*   u     = (const int*)d_in[0];
    const int*   v     = (const int*)d_in[1];
    const float* adj   = (const float*)d_in[3];
    const float* ufeat = (const float*)d_in[4];
    const float* vfeat = (const float*)d_in[5];
    const float* u_w   = (const float*)d_in[6];
    const float* v_w   = (const float*)d_in[7];
    const float* Wu1   = (const float*)d_in[8];
    const float* bu1   = (const float*)d_in[9];
    const float* Wv1   = (const float*)d_in[10];
    const float* bv1   = (const float*)d_in[11];
    const float* Wu2   = (const float*)d_in[12];
    const float* Wv2   = (const float*)d_in[13];
    const float* P     = (const float*)d_in[14];
    const float* a     = (const float*)d_in[15];
    float* out = (float*)d_out;

    void* p;
    cudaGetSymbolAddress(&p, d_cu8);   uint8_t* cu8 = (uint8_t*)p;
    cudaGetSymbolAddress(&p, d_cv8);   uint8_t* cv8 = (uint8_t*)p;
    cudaGetSymbolAddress(&p, d_uh);    float* uh    = (float*)p;
    cudaGetSymbolAddress(&p, d_PT);    float* PT    = (float*)p;
    cudaGetSymbolAddress(&p, d_T0s);   __nv_bfloat16* T0s = (__nv_bfloat16*)p;
    cudaGetSymbolAddress(&p, d_T1s);   __nv_bfloat16* T1s = (__nv_bfloat16*)p;
    cudaGetSymbolAddress(&p, d_vhs);   __nv_bfloat16* vhs = (__nv_bfloat16*)p;
    cudaGetSymbolAddress(&p, d_ufs);   __nv_bfloat16* ufs = (__nv_bfloat16*)p;
    cudaGetSymbolAddress(&p, d_vfs);   __nv_bfloat16* vfs = (__nv_bfloat16*)p;
    cudaGetSymbolAddress(&p, d_w1us);  __nv_bfloat16* w1us = (__nv_bfloat16*)p;
    cudaGetSymbolAddress(&p, d_w1vs);  __nv_bfloat16* w1vs = (__nv_bfloat16*)p;
    cudaGetSymbolAddress(&p, d_ucats); __nv_bfloat16* ucats = (__nv_bfloat16*)p;
    cudaGetSymbolAddress(&p, d_vcats); __nv_bfloat16* vcats = (__nv_bfloat16*)p;
    cudaGetSymbolAddress(&p, d_w2us);  __nv_bfloat16* w2us = (__nv_bfloat16*)p;
    cudaGetSymbolAddress(&p, d_w2vs);  __nv_bfloat16* w2vs = (__nv_bfloat16*)p;

    static cudaStream_t s1 = nullptr;
    static cudaEvent_t evFork = nullptr, evJoin = nullptr;
    if (!s1) {
        cudaStreamCreate(&s1);
        cudaEventCreateWithFlags(&evFork, cudaEventDisableTiming);
        cudaEventCreateWithFlags(&evJoin, cudaEventDisableTiming);
    }

    // ---- fork: stream s1 handles the feature-side chain (champion schedule) ----
    cudaEventRecord(evFork, 0);
    cudaStreamWaitEvent(s1, evFork, 0);

    zero_kernel<<<1, 1, 0, s1>>>();
    splitr_kernel<<<(NE * SIDE) / 1024, 256, 0, s1>>>(ufeat, SIDE, u, ufs, 0);
    splitr_kernel<<<(NE * SIDE) / 1024, 256, 0, s1>>>(vfeat, SIDE, v, vfs, 0);
    splitr_kernel<<<(DIN * SIDE) / 1024, 256, 0, s1>>>(Wu1, SIDE, nullptr, w1us, 1);
    splitr_kernel<<<(DIN * SIDE) / 1024, 256, 0, s1>>>(Wv1, SIDE, nullptr, w1vs, 1);
    splitr_kernel<<<(H1 * CATW) / 1024, 256, 0, s1>>>(Wu2, CATW, nullptr, w2us, 1);
    splitr_kernel<<<(H1 * CATW) / 1024, 256, 0, s1>>>(Wv2, CATW, nullptr, w2vs, 1);
    transP_kernel<<<128, 256, 0, s1>>>(P);
    gemmbf2_kernel<<<dim3(DIN / 64, NE / 128, 2), 256, 0, s1>>>(
        ufs, w1us, bu1, nullptr, ucats, 0,
        vfs, w1vs, bv1, nullptr, vcats, 0,
        0, KFEAT, 1, CATW, H0);
    cudaEventRecord(evJoin, s1);

    // stream 0: adjacency chain (critical path) — champion structure
    cumsum8_kernel<<<(NUI * H0) / 256, 256>>>(u_w, cu8, NUI * H0);
    cumsum8_kernel<<<(NVI * H0) / 256, 256>>>(v_w, cv8, NVI * H0);
    code_kernel<<<16384, 256>>>((const float4*)adj);
    gatherrow_kernel<<<NE, 256>>>(u, v);
    transb_kernel<<<dim3(NE / 32, NE / 32), dim3(32, 32)>>>();
    convfp8_kernel<<<dim3(NE, 2), 256>>>(u, v);

    // join: hidden projections need both chains
    cudaStreamWaitEvent(0, evJoin, 0);
    gemmbf2_kernel<<<dim3(H1 / 64, NE / 128, 2), 256>>>(
        ucats, w2us, nullptr, uh, nullptr, 0,
        vcats, w2vs, nullptr, nullptr, vhs, 1,
        H1, KCAT, 1, H1, 0);
    gemm2_kernel<<<dim3(H1 / 64, NE / 64, 2), 256>>>(uh, PT, T0s, T1s);
    finalmma_kernel<<<dim3(NE / 128, NE / 64), 256>>>(a, out);
    if (out_size >= NE * NE + 2) fin_kernel<<<1, 1>>>(out);
}

// round 17
// speedup vs baseline: 1.0168x; 1.0168x over previous
#include <cuda_runtime.h>
#include <cuda_bf16.h>
#include <cuda_fp16.h>
#include <cuda_fp8.h>
#include <cstdint>
#include <math.h>

#define NUI 4096
#define NVI 4096
#define NC 5
#define H0 256
#define H1 128
#define DIN 512
#define SIDE 1024
#define NE 4096
#define CATW (H0 + DIN)      // 768
#define KF   (3 * H1)        // 384
#define KFEAT (3 * SIDE)     // 3072
#define KCAT (3 * CATW)      // 2304

__device__ uint8_t d_code[(size_t)NUI * NVI];
__device__ uint8_t d_cg [(size_t)NE * NE];
__device__ uint8_t d_cgT[(size_t)NE * NE];
__device__ uint8_t d_cu8[(size_t)NC * NUI * H0];
__device__ uint8_t d_cv8[(size_t)NC * NVI * H0];
__device__ float   d_uh [(size_t)NE * H1];
__device__ float   d_PT [2 * H1 * H1];
__device__ __nv_bfloat16 d_T0s[(size_t)NE * KF];
__device__ __nv_bfloat16 d_T1s[(size_t)NE * KF];
__device__ __nv_bfloat16 d_vhs[(size_t)NE * KF];
__device__ __nv_bfloat16 d_ufs [(size_t)NE * KFEAT];
__device__ __nv_bfloat16 d_vfs [(size_t)NE * KFEAT];
__device__ __nv_bfloat16 d_w1us[(size_t)DIN * KFEAT];
__device__ __nv_bfloat16 d_w1vs[(size_t)DIN * KFEAT];
__device__ __nv_bfloat16 d_ucats[(size_t)NE * KCAT];
__device__ __nv_bfloat16 d_vcats[(size_t)NE * KCAT];
__device__ __nv_bfloat16 d_w2us[(size_t)H1 * KCAT];
__device__ __nv_bfloat16 d_w2vs[(size_t)H1 * KCAT];
__device__ double  g_loss, g_se;
__device__ int     g_cnt;

__device__ __forceinline__ uint32_t smaddr(const void* p) {
    return (uint32_t)__cvta_generic_to_shared(p);
}
__device__ __forceinline__ void ldsm4(uint32_t& r0, uint32_t& r1, uint32_t& r2, uint32_t& r3,
                                      uint32_t a) {
    asm volatile("ldmatrix.sync.aligned.m8n8.x4.shared.b16 {%0,%1,%2,%3}, [%4];\n"
                 : "=r"(r0), "=r"(r1), "=r"(r2), "=r"(r3) : "r"(a));
}
__device__ __forceinline__ void mma16816(float* d, const uint32_t* a, const uint32_t* b) {
    asm volatile("mma.sync.aligned.m16n8k16.row.col.f32.bf16.bf16.f32 "
                 "{%0,%1,%2,%3}, {%4,%5,%6,%7}, {%8,%9}, {%0,%1,%2,%3};\n"
                 : "+f"(d[0]), "+f"(d[1]), "+f"(d[2]), "+f"(d[3])
                 : "r"(a[0]), "r"(a[1]), "r"(a[2]), "r"(a[3]), "r"(b[0]), "r"(b[1]));
}
__device__ __forceinline__ __half2 fp8x2_to_h2(uint32_t w16) {
    __half2_raw r = __nv_cvt_fp8x2_to_halfraw2((__nv_fp8x2_storage_t)w16, __NV_E4M3);
    return *reinterpret_cast<__half2*>(&r);
}
__device__ __forceinline__ uint32_t pack_bf(float x0, float x1) {
    uint32_t u0 = (uint32_t)__bfloat16_as_ushort(__float2bfloat16(x0));
    uint32_t u1 = (uint32_t)__bfloat16_as_ushort(__float2bfloat16(x1));
    return u0 | (u1 << 16);
}
__device__ __forceinline__ float bf_hi(float x) {
    return __bfloat162float(__float2bfloat16(x));
}
__device__ __forceinline__ void split_store2(__nv_bfloat16* S, int SK, int r, int col,
                                             float x0, float x1, int isB) {
    uint32_t hh = pack_bf(x0, x1);
    uint32_t ll = pack_bf(x0 - bf_hi(x0), x1 - bf_hi(x1));
    __nv_bfloat16* d = S + (size_t)r * 3 * SK + col;
    *(uint32_t*)d = hh;
    *(uint32_t*)(d + SK) = isB ? ll : hh;
    *(uint32_t*)(d + 2 * SK) = isB ? hh : ll;
}

__global__ void code_kernel(const float4* __restrict__ adj) {
    size_t t = (size_t)blockIdx.x * 256 + threadIdx.x;
    const size_t S4 = (size_t)NUI * NVI / 4;
    int gx = 0, gy = 0, gz = 0, gw = 0;
#pragma unroll
    for (int c = 0; c < NC; ++c) {
        float4 vv = adj[(size_t)c * S4 + t];
        if (vv.x > 0.5f) gx = c + 1;
        if (vv.y > 0.5f) gy = c + 1;
        if (vv.z > 0.5f) gz = c + 1;
        if (vv.w > 0.5f) gw = c + 1;
    }
    ((uchar4*)d_code)[t] = make_uchar4(gx, gy, gz, gw);
}

__global__ __launch_bounds__(256) void gatherrow_kernel(const int* __restrict__ u,
                                                        const int* __restrict__ v) {
    __shared__ uint8_t srow[NVI];
    int i = blockIdx.x, tid = threadIdx.x;
    const uint32_t* crow = (const uint32_t*)(d_code + (size_t)u[i] * NVI);
    for (int t = tid; t < NVI / 4; t += 256)
        ((uint32_t*)srow)[t] = crow[t];
    __syncthreads();
    uint8_t* orow = d_cg + (size_t)i * NE;
    for (int j = tid * 4; j < NE; j += 1024) {
        uchar4 g = make_uchar4(srow[v[j]], srow[v[j + 1]], srow[v[j + 2]], srow[v[j + 3]]);
        *(uchar4*)(orow + j) = g;
    }
}

__global__ void transb_kernel() {
    __shared__ uint8_t tile[32][33];
    int tx = threadIdx.x, ty = threadIdx.y;
    int i = blockIdx.y * 32 + ty, j = blockIdx.x * 32 + tx;
    tile[ty][tx] = d_cg[(size_t)i * NE + j];
    __syncthreads();
    d_cgT[(size_t)(blockIdx.x * 32 + ty) * NE + blockIdx.y * 32 + tx] = tile[tx][ty];
}

__global__ void cumsum8_kernel(const float* __restrict__ w, uint8_t* __restrict__ out, int n) {
    int idx = blockIdx.x * blockDim.x + threadIdx.x;
    if (idx >= n) return;
    float s = 0.f;
#pragma unroll
    for (int c = 0; c < NC; ++c) {
        s += w[(size_t)c * n + idx];
        out[(size_t)c * n + idx] =
            (uint8_t)__nv_cvt_float_to_fp8(s, __NV_SATFINITE, __NV_E4M3);
    }
}

__global__ void zero_kernel() { g_loss = 0.0; g_se = 0.0; g_cnt = 0; }

// graph conv: sparse gather-sum over fp8 tables (champion form)
__global__ __launch_bounds__(256) void convfp8_kernel(const int* __restrict__ uidx,
                                                      const int* __restrict__ vidx) {
    __shared__ uint8_t rs[NE];
    __shared__ int list[NE];
    __shared__ int wsum[8], wbase[8];
    __shared__ float part[16][H0];
    int z = blockIdx.y;
    const uint8_t* cgm = z ? d_cgT : d_cg;
    const int* idx = z ? uidx : vidx;
    const uint8_t* tab = z ? d_cu8 : d_cv8;
    __nv_bfloat16* outs = z ? d_vcats : d_ucats;

    int i = blockIdx.x, tid = threadIdx.x;
    int lane = tid & 31, wid5 = tid >> 5;
    const uint8_t* row = cgm + (size_t)i * NE;
    for (int t = tid; t < NE / 4; t += 256)
        ((uint32_t*)rs)[t] = ((const uint32_t*)row)[t];
    __syncthreads();

    int j0 = tid * 16;
    int local = 0;
#pragma unroll
    for (int t = 0; t < 16; ++t) if (rs[j0 + t]) local++;
    int val = local;
#pragma unroll
    for (int s = 1; s < 32; s <<= 1) {
        int t = __shfl_up_sync(0xFFFFFFFFu, val, s);
        if (lane >= s) val += t;
    }
    if (lane == 31) wsum[wid5] = val;
    __syncthreads();
    if (tid < 8) {
        int b = 0;
        for (int q = 0; q < tid; ++q) b += wsum[q];
        wbase[tid] = b;
    }
    __syncthreads();
    int pos = wbase[wid5] + val - local;
    int total = wbase[7] + wsum[7];
    for (int t = 0; t < 16; ++t) {
        int g = rs[j0 + t];
        if (g) list[pos++] = (g - 1) * NVI + idx[j0 + t];
    }
    __syncthreads();

    int rg = tid >> 4;
    int hbase = (tid & 15) * 16;
    float facc[16];
#pragma unroll
    for (int q = 0; q < 16; ++q) facc[q] = 0.f;
    int jj = rg;
    while (jj + 256 <= total) {
        __half2 h[8];
#pragma unroll
        for (int q = 0; q < 8; ++q) h[q] = __float2half2_rn(0.f);
#pragma unroll
        for (int w8 = 0; w8 < 16; ++w8) {
            const uint4 w = *(const uint4*)(tab + (size_t)list[jj + w8 * 16] * H0 + hbase);
            h[0] = __hadd2(h[0], fp8x2_to_h2(w.x & 0xFFFFu));
            h[1] = __hadd2(h[1], fp8x2_to_h2(w.x >> 16));
            h[2] = __hadd2(h[2], fp8x2_to_h2(w.y & 0xFFFFu));
            h[3] = __hadd2(h[3], fp8x2_to_h2(w.y >> 16));
            h[4] = __hadd2(h[4], fp8x2_to_h2(w.z & 0xFFFFu));
            h[5] = __hadd2(h[5], fp8x2_to_h2(w.z >> 16));
            h[6] = __hadd2(h[6], fp8x2_to_h2(w.w & 0xFFFFu));
            h[7] = __hadd2(h[7], fp8x2_to_h2(w.w >> 16));
        }
        jj += 256;
#pragma unroll
        for (int q = 0; q < 8; ++q) {
            float2 f = __half22float2(h[q]);
            facc[2 * q] += f.x; facc[2 * q + 1] += f.y;
        }
    }
    while (jj < total) {
        __half2 h[8];
#pragma unroll
        for (int q = 0; q < 8; ++q) h[q] = __float2half2_rn(0.f);
        int lim = jj + 128;
        for (; jj < lim && jj < total; jj += 16) {
            const uint4 w = *(const uint4*)(tab + (size_t)list[jj] * H0 + hbase);
            h[0] = __hadd2(h[0], fp8x2_to_h2(w.x & 0xFFFFu));
            h[1] = __hadd2(h[1], fp8x2_to_h2(w.x >> 16));
            h[2] = __hadd2(h[2], fp8x2_to_h2(w.y & 0xFFFFu));
            h[3] = __hadd2(h[3], fp8x2_to_h2(w.y >> 16));
            h[4] = __hadd2(h[4], fp8x2_to_h2(w.z & 0xFFFFu));
            h[5] = __hadd2(h[5], fp8x2_to_h2(w.z >> 16));
            h[6] = __hadd2(h[6], fp8x2_to_h2(w.w & 0xFFFFu));
            h[7] = __hadd2(h[7], fp8x2_to_h2(w.w >> 16));
        }
#pragma unroll
        for (int q = 0; q < 8; ++q) {
            float2 f = __half22float2(h[q]);
            facc[2 * q] += f.x; facc[2 * q + 1] += f.y;
        }
    }
#pragma unroll
    for (int q = 0; q < 16; q += 4)
        *(float4*)&part[rg][hbase + q] = make_float4(facc[q], facc[q + 1],
                                                     facc[q + 2], facc[q + 3]);
    __syncthreads();
    float s = 0.f;
#pragma unroll
    for (int r = 0; r < 16; ++r) s += part[r][tid];
    float inv = total ? 1.f / (float)total : 0.f;
    float zv = fmaxf(s * inv, 0.f);
    __nv_bfloat16 hb = __float2bfloat16(zv);
    __nv_bfloat16 lb = __float2bfloat16(zv - __bfloat162float(hb));
    __nv_bfloat16* d = outs + (size_t)i * KCAT + tid;
    d[0] = hb; d[CATW] = hb; d[2 * CATW] = lb;
}

__global__ void splitr_kernel(const float* __restrict__ src, int K,
                              const int* __restrict__ idx,
                              __nv_bfloat16* __restrict__ dst, int isB) {
    int t = blockIdx.x * 256 + threadIdx.x;
    int q = t * 4;
    int row = q / K, k = q - row * K;
    const float4 x = *(const float4*)(src + (size_t)(idx ? idx[row] : row) * K + k);
    uint2 hh = make_uint2(pack_bf(x.x, x.y), pack_bf(x.z, x.w));
    uint2 ll = make_uint2(pack_bf(x.x - bf_hi(x.x), x.y - bf_hi(x.y)),
                          pack_bf(x.z - bf_hi(x.z), x.w - bf_hi(x.w)));
    __nv_bfloat16* d = dst + (size_t)row * 3 * K + k;
    *(uint2*)d = hh;
    *(uint2*)(d + K) = isB ? ll : hh;
    *(uint2*)(d + 2 * K) = isB ? hh : ll;
}

// batched (z=2) double-buffered bf16 HMMA GEMM with optional fp32 C / split-bf16 S output.
__global__ __launch_bounds__(256) void gemmbf2_kernel(
    const __nv_bfloat16* __restrict__ A0, const __nv_bfloat16* __restrict__ B0,
    const float* __restrict__ bias0, float* __restrict__ C0,
    __nv_bfloat16* __restrict__ S0, int SisB0,
    const __nv_bfloat16* __restrict__ A1, const __nv_bfloat16* __restrict__ B1,
    const float* __restrict__ bias1, float* __restrict__ C1,
    __nv_bfloat16* __restrict__ S1, int SisB1,
    int ldc, int KS, int doRelu, int SK, int SOFF) {
    __shared__ __align__(16) __nv_bfloat16 As[2][128][40];
    __shared__ __align__(16) __nv_bfloat16 Bs[2][64][40];
    const uint32_t AOFF = 128 * 40 * 2;
    const uint32_t BOFF = 64 * 40 * 2;
    int z = blockIdx.z;
    const __nv_bfloat16* A = z ? A1 : A0;
    const __nv_bfloat16* B = z ? B1 : B0;
    const float* bias = z ? bias1 : bias0;
    float* C = z ? C1 : C0;
    __nv_bfloat16* S = z ? S1 : S0;
    int SisB = z ? SisB1 : SisB0;

    int bm = blockIdx.y * 128, bn = blockIdx.x * 64;
    int tid = threadIdx.x, lane = tid & 31, warp = tid >> 5;
    int wm = (warp & 3) * 32, wn = (warp >> 2) * 32;
    int rowL = tid >> 1, segL = (tid & 1) * 16;

    float acc[2][4][4] = {};
    uint32_t aAddr[2], bAddr[2];
#pragma unroll
    for (int f = 0; f < 2; ++f)
        aAddr[f] = smaddr(&As[0][wm + f * 16 + (lane & 15)][(lane >> 4) * 8]);
#pragma unroll
    for (int p = 0; p < 2; ++p)
        bAddr[p] = smaddr(&Bs[0][wn + p * 16 + (lane & 7) + ((lane >> 4) & 1) * 8]
                             [((lane >> 3) & 1) * 8]);

    const __nv_bfloat16* arow = A + (size_t)(bm + rowL) * KS + segL;
    const __nv_bfloat16* brow = B + (size_t)(bn + (rowL & 63)) * KS + segL;

    {
        uint4 a0 = ((const uint4*)arow)[0], a1 = ((const uint4*)arow)[1];
        ((uint4*)&As[0][rowL][segL])[0] = a0; ((uint4*)&As[0][rowL][segL])[1] = a1;
        if (tid < 128) {
            uint4 b0 = ((const uint4*)brow)[0], b1 = ((const uint4*)brow)[1];
            ((uint4*)&Bs[0][rowL][segL])[0] = b0; ((uint4*)&Bs[0][rowL][segL])[1] = b1;
        }
    }
    __syncthreads();

    int cur = 0;
    for (int k0 = 0; k0 < KS; k0 += 32) {
        bool nxt = (k0 + 32 < KS);
        uint4 pa0, pa1, pb0, pb1;
        if (nxt) {
            pa0 = ((const uint4*)(arow + k0 + 32))[0];
            pa1 = ((const uint4*)(arow + k0 + 32))[1];
            if (tid < 128) {
                pb0 = ((const uint4*)(brow + k0 + 32))[0];
                pb1 = ((const uint4*)(brow + k0 + 32))[1];
            }
        }
        uint32_t ao = cur ? AOFF : 0, bo = cur ? BOFF : 0;
#pragma unroll
        for (int ks = 0; ks < 2; ++ks) {
            uint32_t a[2][4], b[4][2];
            ldsm4(a[0][0], a[0][1], a[0][2], a[0][3], aAddr[0] + ao + ks * 32);
            ldsm4(a[1][0], a[1][1], a[1][2], a[1][3], aAddr[1] + ao + ks * 32);
#pragma unroll
            for (int p = 0; p < 2; ++p) {
                uint32_t r0, r1, r2, r3;
                ldsm4(r0, r1, r2, r3, bAddr[p] + bo + ks * 32);
                b[2 * p][0] = r0; b[2 * p][1] = r1;
                b[2 * p + 1][0] = r2; b[2 * p + 1][1] = r3;
            }
#pragma unroll
            for (int f = 0; f < 2; ++f)
#pragma unroll
                for (int e = 0; e < 4; ++e)
                    mma16816(acc[f][e], a[f], b[e]);
        }
        if (nxt) {
            int nx = cur ^ 1;
            ((uint4*)&As[nx][rowL][segL])[0] = pa0; ((uint4*)&As[nx][rowL][segL])[1] = pa1;
            if (tid < 128) {
                ((uint4*)&Bs[nx][rowL][segL])[0] = pb0; ((uint4*)&Bs[nx][rowL][segL])[1] = pb1;
            }
        }
        __syncthreads();
        cur ^= 1;
    }
#pragma unroll
    for (int f = 0; f < 2; ++f) {
        int r0 = bm + wm + f * 16 + (lane >> 2);
#pragma unroll
        for (int e = 0; e < 4; ++e) {
            int col = bn + wn + e * 8 + (lane & 3) * 2;
            float b0 = bias ? bias[col] : 0.f;
            float b1 = bias ? bias[col + 1] : 0.f;
            float c00 = acc[f][e][0] + b0, c01 = acc[f][e][1] + b1;
            float c10 = acc[f][e][2] + b0, c11 = acc[f][e][3] + b1;
            if (doRelu) {
                c00 = fmaxf(c00, 0.f); c01 = fmaxf(c01, 0.f);
                c10 = fmaxf(c10, 0.f); c11 = fmaxf(c11, 0.f);
            }
            if (C) {
                *(float2*)&C[(size_t)r0 * ldc + col] = make_float2(c00, c01);
                *(float2*)&C[(size_t)(r0 + 8) * ldc + col] = make_float2(c10, c11);
            }
            if (S) {
                split_store2(S, SK, r0,     SOFF + col, c00, c01, SisB);
                split_store2(S, SK, r0 + 8, SOFF + col, c10, c11, SisB);
            }
        }
    }
}

__global__ void gemm2_kernel(const float* __restrict__ A,
                             const float* __restrict__ Pt,
                             __nv_bfloat16* __restrict__ S0,
                             __nv_bfloat16* __restrict__ S1) {
    __shared__ float As[16][64];
    __shared__ float Bs[16][64];
    int z = blockIdx.z;
    const float* B = Pt + (size_t)z * H1 * H1;
    __nv_bfloat16* S = z ? S1 : S0;
    int bm = blockIdx.y * 64, bn = blockIdx.x * 64;
    int tid = threadIdx.x;
    int tx = tid & 15, ty = tid >> 4;
    int lrow = tid >> 2, lk = (tid & 3) * 4;
    const float* Ap = A + (size_t)(bm + lrow) * H1 + lk;
    const float* Bp = B + (size_t)(bn + lrow) * H1 + lk;
    float acc[4][4] = {};
    for (int k0 = 0; k0 < H1; k0 += 16) {
        float4 av = *(const float4*)(Ap + k0);
        float4 bv = *(const float4*)(Bp + k0);
        __syncthreads();
        As[lk + 0][lrow] = av.x; As[lk + 1][lrow] = av.y;
        As[lk + 2][lrow] = av.z; As[lk + 3][lrow] = av.w;
        Bs[lk + 0][lrow] = bv.x; Bs[lk + 1][lrow] = bv.y;
        Bs[lk + 2][lrow] = bv.z; Bs[lk + 3][lrow] = bv.w;
        __syncthreads();
#pragma unroll
        for (int k = 0; k < 16; ++k) {
            float4 a = *(const float4*)&As[k][ty * 4];
            float4 b = *(const float4*)&Bs[k][tx * 4];
            float af[4] = {a.x, a.y, a.z, a.w};
            float bf[4] = {b.x, b.y, b.z, b.w};
#pragma unroll
            for (int p = 0; p < 4; ++p)
#pragma unroll
                for (int q = 0; q < 4; ++q)
                    acc[p][q] = fmaf(af[p], bf[q], acc[p][q]);
        }
    }
#pragma unroll
    for (int p = 0; p < 4; ++p) {
        int row = bm + ty * 4 + p;
        int col = bn + tx * 4;
        split_store2(S, H1, row, col,     acc[p][0], acc[p][1], 0);
        split_store2(S, H1, row, col + 2, acc[p][2], acc[p][3], 0);
    }
}

__global__ void transP_kernel(const float* __restrict__ P) {
    int t = blockIdx.x * 256 + threadIdx.x;
    int b = t >> 14, rem = t & 16383;
    int d = rem >> 7, e = rem & 127;
    d_PT[(size_t)b * 16384 + e * 128 + d] = P[t];
}

__device__ __forceinline__ float fast_exp(float x) {
    float t = x * 1.4426950408889634f;
    float r = rintf(t);
    float f = t - r;
    float p = 1.535336188319500e-4f;
    p = fmaf(p, f, 1.339887440266574e-3f);
    p = fmaf(p, f, 9.618437357674640e-3f);
    p = fmaf(p, f, 5.550332471162809e-2f);
    p = fmaf(p, f, 2.402264791363012e-1f);
    p = fmaf(p, f, 6.931472028550421e-1f);
    p = fmaf(p, f, 1.0f);
    int e = (int)r;
    if (e < -126) e = -126;
    return p * __int_as_float((e + 127) << 23);
}

__device__ __forceinline__ void decode_pair(float s0a, float s1a, float s0b, float s1b,
                                            const float* a0c, const float* a1c,
                                            int i, int jc, float* __restrict__ out,
                                            float& lloss, float& lsse, int& lcnt) {
    float la[5], lb[5], mxa = -1e30f, mxb = -1e30f;
#pragma unroll
    for (int c = 0; c < 5; ++c) {
        la[c] = fmaf(a0c[c], s0a, a1c[c] * s1a);
        lb[c] = fmaf(a0c[c], s0b, a1c[c] * s1b);
        mxa = fmaxf(mxa, la[c]);
        mxb = fmaxf(mxb, lb[c]);
    }
    float ssa = 0.f, ssb = 0.f, mha = 0.f, mhb = 0.f;
#pragma unroll
    for (int c = 0; c < 5; ++c) {
        float ea = fast_exp(la[c] - mxa);
        float eb = fast_exp(lb[c] - mxb);
        ssa += ea; ssb += eb;
        mha = fmaf((float)(c + 1), ea, mha);
        mhb = fmaf((float)(c + 1), eb, mhb);
    }
    mha *= 1.f / ssa;
    mhb *= 1.f / ssb;
    *(float2*)&out[(size_t)i * NE + jc] = make_float2(mha, mhb);
    uchar2 g2 = *(const uchar2*)(d_cg + (size_t)i * NE + jc);
    if (g2.x) {
        float lse = mxa + __logf(ssa);
        float lg = la[0];
#pragma unroll
        for (int c = 1; c < 5; ++c) if (g2.x == c + 1) lg = la[c];
        lloss += lse - lg;
        float dd = mha - (float)g2.x;
        lsse += dd * dd;
        lcnt++;
    }
    if (g2.y) {
        float lse = mxb + __logf(ssb);
        float lg = lb[0];
#pragma unroll
        for (int c = 1; c < 5; ++c) if (g2.y == c + 1) lg = lb[c];
        lloss += lse - lg;
        float dd = mhb - (float)g2.y;
        lsse += dd * dd;
        lcnt++;
    }
}

// fused decoder on HMMA (split-bf16), BM=64 x BN=128 (R15 champion form),
// warp-shuffle loss reduction
__global__ __launch_bounds__(256) void finalmma_kernel(const float* __restrict__ avec,
                                                       float* __restrict__ out) {
    __shared__ __align__(16) __nv_bfloat16 As0[64][40];
    __shared__ __align__(16) __nv_bfloat16 As1[64][40];
    __shared__ __align__(16) __nv_bfloat16 Bs[128][40];
    int bm = blockIdx.y * 64, bn = blockIdx.x * 128;
    int tid = threadIdx.x, lane = tid & 31, warp = tid >> 5;
    int wm = (warp & 1) * 32, wn = (warp >> 1) * 32;
    int rowL = tid >> 1, segL = (tid & 1) * 16;

    float acc0[2][4][4] = {}, acc1[2][4][4] = {};
    uint32_t a0Addr[2], a1Addr[2], bAddr[2];
#pragma unroll
    for (int f = 0; f < 2; ++f) {
        a0Addr[f] = smaddr(&As0[wm + f * 16 + (lane & 15)][(lane >> 4) * 8]);
        a1Addr[f] = smaddr(&As1[wm + f * 16 + (lane & 15)][(lane >> 4) * 8]);
    }
#pragma unroll
    for (int p = 0; p < 2; ++p)
        bAddr[p] = smaddr(&Bs[wn + p * 16 + (lane & 7) + ((lane >> 4) & 1) * 8]
                             [((lane >> 3) & 1) * 8]);

    const __nv_bfloat16* a0row = d_T0s + (size_t)(bm + (rowL & 63)) * KF + segL;
    const __nv_bfloat16* a1row = d_T1s + (size_t)(bm + (rowL & 63)) * KF + segL;
    const __nv_bfloat16* brow  = d_vhs + (size_t)(bn + rowL) * KF + segL;

    uint4 p0a, p0b, p1a, p1b;
    if (tid < 128) {
        p0a = ((const uint4*)a0row)[0]; p0b = ((const uint4*)a0row)[1];
        p1a = ((const uint4*)a1row)[0]; p1b = ((const uint4*)a1row)[1];
    }
    uint4 pba = ((const uint4*)brow)[0], pbb = ((const uint4*)brow)[1];

    for (int k0 = 0; k0 < KF; k0 += 32) {
        __syncthreads();
        if (tid < 128) {
            ((uint4*)&As0[rowL][segL])[0] = p0a; ((uint4*)&As0[rowL][segL])[1] = p0b;
            ((uint4*)&As1[rowL][segL])[0] = p1a; ((uint4*)&As1[rowL][segL])[1] = p1b;
        }
        ((uint4*)&Bs[rowL][segL])[0] = pba; ((uint4*)&Bs[rowL][segL])[1] = pbb;
        __syncthreads();
        if (k0 + 32 < KF) {
            if (tid < 128) {
                p0a = ((const uint4*)(a0row + k0 + 32))[0];
                p0b = ((const uint4*)(a0row + k0 + 32))[1];
                p1a = ((const uint4*)(a1row + k0 + 32))[0];
                p1b = ((const uint4*)(a1row + k0 + 32))[1];
            }
            pba = ((const uint4*)(brow + k0 + 32))[0];
            pbb = ((const uint4*)(brow + k0 + 32))[1];
        }
#pragma unroll
        for (int ks = 0; ks < 2; ++ks) {
            uint32_t a0[2][4], a1[2][4], b[4][2];
            ldsm4(a0[0][0], a0[0][1], a0[0][2], a0[0][3], a0Addr[0] + ks * 32);
            ldsm4(a0[1][0], a0[1][1], a0[1][2], a0[1][3], a0Addr[1] + ks * 32);
            ldsm4(a1[0][0], a1[0][1], a1[0][2], a1[0][3], a1Addr[0] + ks * 32);
            ldsm4(a1[1][0], a1[1][1], a1[1][2], a1[1][3], a1Addr[1] + ks * 32);
#pragma unroll
            for (int p = 0; p < 2; ++p) {
                uint32_t r0, r1, r2, r3;
                ldsm4(r0, r1, r2, r3, bAddr[p] + ks * 32);
                b[2 * p][0] = r0; b[2 * p][1] = r1;
                b[2 * p + 1][0] = r2; b[2 * p + 1][1] = r3;
            }
#pragma unroll
            for (int f = 0; f < 2; ++f)
#pragma unroll
                for (int e = 0; e < 4; ++e) {
                    mma16816(acc0[f][e], a0[f], b[e]);
                    mma16816(acc1[f][e], a1[f], b[e]);
                }
        }
    }

    float a0c[5], a1c[5];
#pragma unroll
    for (int c = 0; c < 5; ++c) { a0c[c] = avec[c]; a1c[c] = avec[5 + c]; }
    float lloss = 0.f, lsse = 0.f;
    int lcnt = 0;
#pragma unroll
    for (int f = 0; f < 2; ++f) {
        int i0 = bm + wm + f * 16 + (lane >> 2);
#pragma unroll
        for (int e = 0; e < 4; ++e) {
            int jc = bn + wn + e * 8 + (lane & 3) * 2;
            decode_pair(acc0[f][e][0], acc1[f][e][0], acc0[f][e][1], acc1[f][e][1],
                        a0c, a1c, i0, jc, out, lloss, lsse, lcnt);
            decode_pair(acc0[f][e][2], acc1[f][e][2], acc0[f][e][3], acc1[f][e][3],
                        a0c, a1c, i0 + 8, jc, out, lloss, lsse, lcnt);
        }
    }

    // warp-shuffle pre-reduction, then one smem stage + thread-0 finish
#pragma unroll
    for (int s = 16; s; s >>= 1) {
        lloss += __shfl_xor_sync(0xFFFFFFFFu, lloss, s);
        lsse  += __shfl_xor_sync(0xFFFFFFFFu, lsse, s);
        lcnt  += __shfl_xor_sync(0xFFFFFFFFu, lcnt, s);
    }
    __shared__ float wls[8], wse[8];
    __shared__ int wct[8];
    if (lane == 0) { wls[warp] = lloss; wse[warp] = lsse; wct[warp] = lcnt; }
    __syncthreads();
    if (tid == 0) {
        double tl = 0.0, ts = 0.0;
        int tc = 0;
#pragma unroll
        for (int q = 0; q < 8; ++q) { tl += wls[q]; ts += wse[q]; tc += wct[q]; }
        atomicAdd(&g_loss, tl);
        atomicAdd(&g_se, ts);
        atomicAdd(&g_cnt, tc);
    }
}

__global__ void fin_kernel(float* __restrict__ out) {
    double n = (g_cnt > 0) ? (double)g_cnt : 1.0;
    out[(size_t)NE * NE + 0] = (float)(g_loss / n);
    out[(size_t)NE * NE + 1] = (float)sqrt(g_se / n);
}

extern "C" void kernel_launch(void* const* d_in, const int* in_sizes, int n_in,
                              void* d_out, int out_size) {
    const int*   u     = (const int*)d_in[0];
    const int*   v     = (const int*)d_in[1];
    const float* adj   = (const float*)d_in[3];
    const float* ufeat = (const float*)d_in[4];
    const float* vfeat = (const float*)d_in[5];
    const float* u_w   = (const float*)d_in[6];
    const float* v_w   = (const float*)d_in[7];
    const float* Wu1   = (const float*)d_in[8];
    const float* bu1   = (const float*)d_in[9];
    const float* Wv1   = (const float*)d_in[10];
    const float* bv1   = (const float*)d_in[11];
    const float* Wu2   = (const float*)d_in[12];
    const float* Wv2   = (const float*)d_in[13];
    const float* P     = (const float*)d_in[14];
    const float* a     = (const float*)d_in[15];
    float* out = (float*)d_out;

    void* p;
    cudaGetSymbolAddress(&p, d_cu8);   uint8_t* cu8 = (uint8_t*)p;
    cudaGetSymbolAddress(&p, d_cv8);   uint8_t* cv8 = (uint8_t*)p;
    cudaGetSymbolAddress(&p, d_uh);    float* uh    = (float*)p;
    cudaGetSymbolAddress(&p, d_PT);    float* PT    = (float*)p;
    cudaGetSymbolAddress(&p, d_T0s);   __nv_bfloat16* T0s = (__nv_bfloat16*)p;
    cudaGetSymbolAddress(&p, d_T1s);   __nv_bfloat16* T1s = (__nv_bfloat16*)p;
    cudaGetSymbolAddress(&p, d_vhs);   __nv_bfloat16* vhs = (__nv_bfloat16*)p;
    cudaGetSymbolAddress(&p, d_ufs);   __nv_bfloat16* ufs = (__nv_bfloat16*)p;
    cudaGetSymbolAddress(&p, d_vfs);   __nv_bfloat16* vfs = (__nv_bfloat16*)p;
    cudaGetSymbolAddress(&p, d_w1us);  __nv_bfloat16* w1us = (__nv_bfloat16*)p;
    cudaGetSymbolAddress(&p, d_w1vs);  __nv_bfloat16* w1vs = (__nv_bfloat16*)p;
    cudaGetSymbolAddress(&p, d_ucats); __nv_bfloat16* ucats = (__nv_bfloat16*)p;
    cudaGetSymbolAddress(&p, d_vcats); __nv_bfloat16* vcats = (__nv_bfloat16*)p;
    cudaGetSymbolAddress(&p, d_w2us);  __nv_bfloat16* w2us = (__nv_bfloat16*)p;
    cudaGetSymbolAddress(&p, d_w2vs);  __nv_bfloat16* w2vs = (__nv_bfloat16*)p;

    static cudaStream_t s1 = nullptr;
    static cudaEvent_t evFork = nullptr, evJoin = nullptr;
    if (!s1) {
        cudaStreamCreate(&s1);
        cudaEventCreateWithFlags(&evFork, cudaEventDisableTiming);
        cudaEventCreateWithFlags(&evJoin, cudaEventDisableTiming);
    }

    // ---- fork: stream s1 handles the feature-side chain (champion schedule) ----
    cudaEventRecord(evFork, 0);
    cudaStreamWaitEvent(s1, evFork, 0);

    zero_kernel<<<1, 1, 0, s1>>>();
    splitr_kernel<<<(NE * SIDE) / 1024, 256, 0, s1>>>(ufeat, SIDE, u, ufs, 0);
    splitr_kernel<<<(NE * SIDE) / 1024, 256, 0, s1>>>(vfeat, SIDE, v, vfs, 0);
    splitr_kernel<<<(DIN * SIDE) / 1024, 256, 0, s1>>>(Wu1, SIDE, nullptr, w1us, 1);
    splitr_kernel<<<(DIN * SIDE) / 1024, 256, 0, s1>>>(Wv1, SIDE, nullptr, w1vs, 1);
    splitr_kernel<<<(H1 * CATW) / 1024, 256, 0, s1>>>(Wu2, CATW, nullptr, w2us, 1);
    splitr_kernel<<<(H1 * CATW) / 1024, 256, 0, s1>>>(Wv2, CATW, nullptr, w2vs, 1);
    transP_kernel<<<128, 256, 0, s1>>>(P);
    gemmbf2_kernel<<<dim3(DIN / 64, NE / 128, 2), 256, 0, s1>>>(
        ufs, w1us, bu1, nullptr, ucats, 0,
        vfs, w1vs, bv1, nullptr, vcats, 0,
        0, KFEAT, 1, CATW, H0);
    cudaEventRecord(evJoin, s1);

    // stream 0: adjacency chain (critical path) — champion structure
    cumsum8_kernel<<<(NUI * H0) / 256, 256>>>(u_w, cu8, NUI * H0);
    cumsum8_kernel<<<(NVI * H0) / 256, 256>>>(v_w, cv8, NVI * H0);
    code_kernel<<<16384, 256>>>((const float4*)adj);
    gatherrow_kernel<<<NE, 256>>>(u, v);
    transb_kernel<<<dim3(NE / 32, NE / 32), dim3(32, 32)>>>();
    convfp8_kernel<<<dim3(NE, 2), 256>>>(u, v);

    // join: hidden projections need both chains
    cudaStreamWaitEvent(0, evJoin, 0);
    gemmbf2_kernel<<<dim3(H1 / 64, NE / 128, 2), 256>>>(
        ucats, w2us, nullptr, uh, nullptr, 0,
        vcats, w2vs, nullptr, nullptr, vhs, 1,
        H1, KCAT, 1, H1, 0);
    gemm2_kernel<<<dim3(H1 / 64, NE / 64, 2), 256>>>(uh, PT, T0s, T1s);
    finalmma_kernel<<<dim3(NE / 128, NE / 64), 256>>>(a, out);
    if (out_size >= NE * NE + 2) fin_kernel<<<1, 1>>>(out);
}